// round 1
// baseline (speedup 1.0000x reference)
#include <cuda_runtime.h>
#include <math.h>

#define BB 4
#define LL 2048
#define DD 1024
#define HH 16
#define DHD 64
#define ROWS (BB*LL)   // 8192

// Scratch (allocation-free rule: __device__ globals)
__device__ float g_q[ROWS*DD];
__device__ float g_k[ROWS*DD];
__device__ float g_v[ROWS*DD];
__device__ float g_att[ROWS*DD];
__device__ float g_proj[ROWS*DD];

// ---------------------------------------------------------------------------
// C[M,N] = A[M,K] @ W[N,K]^T + bias[N]
// 128x128 block tile, K-step 16, 256 threads, 8x8 per-thread register tile.
// ---------------------------------------------------------------------------
__global__ __launch_bounds__(256) void gemm_bias_kernel(
    const float* __restrict__ A, const float* __restrict__ W,
    const float* __restrict__ bias, float* __restrict__ C,
    int M, int N, int K)
{
    __shared__ float As[16][132];
    __shared__ float Ws[16][132];

    const int tid = threadIdx.x;
    const int tx  = tid & 15;
    const int ty  = tid >> 4;
    const int m0  = blockIdx.y * 128;
    const int n0  = blockIdx.x * 128;

    float acc[8][8];
#pragma unroll
    for (int i = 0; i < 8; i++)
#pragma unroll
        for (int j = 0; j < 8; j++) acc[i][j] = 0.0f;

    for (int k0 = 0; k0 < K; k0 += 16) {
#pragma unroll
        for (int jj = 0; jj < 2; jj++) {
            int i   = tid + 256 * jj;     // 0..511
            int row = i >> 2;             // 0..127
            int c4  = i & 3;              // 0..3
            float4 av = *(const float4*)(A + (m0 + row) * K + k0 + c4 * 4);
            float4 wv = *(const float4*)(W + (n0 + row) * K + k0 + c4 * 4);
            As[c4*4+0][row] = av.x; As[c4*4+1][row] = av.y;
            As[c4*4+2][row] = av.z; As[c4*4+3][row] = av.w;
            Ws[c4*4+0][row] = wv.x; Ws[c4*4+1][row] = wv.y;
            Ws[c4*4+2][row] = wv.z; Ws[c4*4+3][row] = wv.w;
        }
        __syncthreads();

#pragma unroll
        for (int kk = 0; kk < 16; kk++) {
            float a[8], w[8];
            *(float4*)&a[0] = *(const float4*)&As[kk][ty * 8];
            *(float4*)&a[4] = *(const float4*)&As[kk][ty * 8 + 4];
            *(float4*)&w[0] = *(const float4*)&Ws[kk][tx * 8];
            *(float4*)&w[4] = *(const float4*)&Ws[kk][tx * 8 + 4];
#pragma unroll
            for (int i = 0; i < 8; i++)
#pragma unroll
                for (int j = 0; j < 8; j++)
                    acc[i][j] = fmaf(a[i], w[j], acc[i][j]);
        }
        __syncthreads();
    }

#pragma unroll
    for (int i = 0; i < 8; i++) {
        int r = m0 + ty * 8 + i;
#pragma unroll
        for (int j = 0; j < 8; j += 4) {
            int c = n0 + tx * 8 + j;
            float4 o;
            o.x = acc[i][j+0] + bias[c+0];
            o.y = acc[i][j+1] + bias[c+1];
            o.z = acc[i][j+2] + bias[c+2];
            o.w = acc[i][j+3] + bias[c+3];
            *(float4*)(C + r * N + c) = o;
        }
    }
}

// ---------------------------------------------------------------------------
// Flash attention: one query row per thread (128 rows/block), K-tile = 32.
// Q/K/V live in the (B,L,D) projection buffers; head h occupies columns
// [h*64, h*64+64). Online softmax, mask applied as -1e9 pre-softmax.
// Grid: (L/128, H, B), block: 128 threads.
// ---------------------------------------------------------------------------
__global__ __launch_bounds__(128) void flash_kernel(
    const float* __restrict__ Q, const float* __restrict__ Kx,
    const float* __restrict__ V, const int* __restrict__ mask,
    float* __restrict__ O)
{
    const int b  = blockIdx.z;
    const int h  = blockIdx.y;
    const int q0 = blockIdx.x * 128;
    const int tid = threadIdx.x;

    __shared__ float4 Ks[32 * 16];
    __shared__ float4 Vs[32 * 16];
    __shared__ int    Ms[32];

    const int headOff = h * DHD;
    const int rowBase = (b * LL + q0 + tid) * DD + headOff;

    float4 q4[16];
#pragma unroll
    for (int i = 0; i < 16; i++)
        q4[i] = *(const float4*)(Q + rowBase + i * 4);

    float4 acc4[16];
#pragma unroll
    for (int i = 0; i < 16; i++) acc4[i] = make_float4(0.f, 0.f, 0.f, 0.f);

    float m = -1e30f, l = 0.0f;

    for (int k0 = 0; k0 < LL; k0 += 32) {
#pragma unroll
        for (int j = 0; j < 4; j++) {
            int i = tid + 128 * j;      // 0..511
            int r = i >> 4;             // 0..31
            int c = i & 15;             // 0..15
            int g = (b * LL + k0 + r) * DD + headOff + c * 4;
            Ks[r * 16 + c] = *(const float4*)(Kx + g);
            Vs[r * 16 + c] = *(const float4*)(V + g);
        }
        if (tid < 32) Ms[tid] = mask[b * LL + k0 + tid];
        __syncthreads();

        float s[32];
        float tmax = -1e30f;
#pragma unroll
        for (int j = 0; j < 32; j++) {
            float s0 = 0.f, s1 = 0.f, s2 = 0.f, s3 = 0.f;
#pragma unroll
            for (int d = 0; d < 16; d++) {
                float4 kv = Ks[j * 16 + d];
                s0 = fmaf(q4[d].x, kv.x, s0);
                s1 = fmaf(q4[d].y, kv.y, s1);
                s2 = fmaf(q4[d].z, kv.z, s2);
                s3 = fmaf(q4[d].w, kv.w, s3);
            }
            float sv = ((s0 + s1) + (s2 + s3)) * 0.125f;   // / sqrt(64)
            sv = (Ms[j] == 0) ? -1e9f : sv;
            s[j] = sv;
            tmax = fmaxf(tmax, sv);
        }

        float mnew  = fmaxf(m, tmax);
        float scale = __expf(m - mnew);
        l *= scale;
#pragma unroll
        for (int i = 0; i < 16; i++) {
            acc4[i].x *= scale; acc4[i].y *= scale;
            acc4[i].z *= scale; acc4[i].w *= scale;
        }

#pragma unroll
        for (int j = 0; j < 32; j++) {
            float p = __expf(s[j] - mnew);
            l += p;
#pragma unroll
            for (int d = 0; d < 16; d++) {
                float4 vv = Vs[j * 16 + d];
                acc4[d].x = fmaf(p, vv.x, acc4[d].x);
                acc4[d].y = fmaf(p, vv.y, acc4[d].y);
                acc4[d].z = fmaf(p, vv.z, acc4[d].z);
                acc4[d].w = fmaf(p, vv.w, acc4[d].w);
            }
        }
        m = mnew;
        __syncthreads();
    }

    float inv = 1.0f / l;
#pragma unroll
    for (int i = 0; i < 16; i++) {
        float4 o;
        o.x = acc4[i].x * inv; o.y = acc4[i].y * inv;
        o.z = acc4[i].z * inv; o.w = acc4[i].w * inv;
        *(float4*)(O + rowBase + i * 4) = o;
    }
}

// ---------------------------------------------------------------------------
// x = proj + resid ; out = LayerNorm(x) * gamma + beta  (population variance)
// One row (D=1024) per 256-thread block, float4 per thread.
// ---------------------------------------------------------------------------
__global__ __launch_bounds__(256) void ln_kernel(
    const float* __restrict__ proj, const float* __restrict__ resid,
    const float* __restrict__ gamma, const float* __restrict__ beta,
    float* __restrict__ out)
{
    const int row = blockIdx.x;
    const int tid = threadIdx.x;

    float4 p = ((const float4*)(proj  + row * DD))[tid];
    float4 r = ((const float4*)(resid + row * DD))[tid];
    float4 x = make_float4(p.x + r.x, p.y + r.y, p.z + r.z, p.w + r.w);

    float s  = x.x + x.y + x.z + x.w;
    float ss = x.x * x.x + x.y * x.y + x.z * x.z + x.w * x.w;

#pragma unroll
    for (int off = 16; off > 0; off >>= 1) {
        s  += __shfl_xor_sync(0xffffffffu, s,  off);
        ss += __shfl_xor_sync(0xffffffffu, ss, off);
    }

    __shared__ float rs[8], rss[8];
    __shared__ float mu_s, rstd_s;
    const int wid  = tid >> 5;
    const int lane = tid & 31;
    if (lane == 0) { rs[wid] = s; rss[wid] = ss; }
    __syncthreads();
    if (tid == 0) {
        float S = 0.f, SS = 0.f;
#pragma unroll
        for (int i = 0; i < 8; i++) { S += rs[i]; SS += rss[i]; }
        float mu  = S * (1.0f / DD);
        float var = SS * (1.0f / DD) - mu * mu;
        mu_s   = mu;
        rstd_s = rsqrtf(var + 1e-5f);
    }
    __syncthreads();

    float mu = mu_s, rstd = rstd_s;
    float4 g  = ((const float4*)gamma)[tid];
    float4 be = ((const float4*)beta)[tid];
    float4 o;
    o.x = (x.x - mu) * rstd * g.x + be.x;
    o.y = (x.y - mu) * rstd * g.y + be.y;
    o.z = (x.z - mu) * rstd * g.z + be.z;
    o.w = (x.w - mu) * rstd * g.w + be.w;
    ((float4*)(out + row * DD))[tid] = o;
}

// ---------------------------------------------------------------------------
extern "C" void kernel_launch(void* const* d_in, const int* in_sizes, int n_in,
                              void* d_out, int out_size)
{
    const float* query = (const float*)d_in[0];
    const float* key_  = (const float*)d_in[1];
    const float* value = (const float*)d_in[2];
    const int*   mask  = (const int*  )d_in[3];
    const float* Wq    = (const float*)d_in[4];
    const float* bq    = (const float*)d_in[5];
    const float* Wk    = (const float*)d_in[6];
    const float* bk    = (const float*)d_in[7];
    const float* Wv    = (const float*)d_in[8];
    const float* bv    = (const float*)d_in[9];
    const float* Wo    = (const float*)d_in[10];
    const float* bo    = (const float*)d_in[11];
    const float* gamma = (const float*)d_in[12];
    const float* beta  = (const float*)d_in[13];
    float* out = (float*)d_out;

    float *q, *k, *v, *att, *proj;
    cudaGetSymbolAddress((void**)&q,    g_q);
    cudaGetSymbolAddress((void**)&k,    g_k);
    cudaGetSymbolAddress((void**)&v,    g_v);
    cudaGetSymbolAddress((void**)&att,  g_att);
    cudaGetSymbolAddress((void**)&proj, g_proj);

    dim3 ggrid(DD / 128, ROWS / 128);   // (8, 64)
    gemm_bias_kernel<<<ggrid, 256>>>(query, Wq, bq, q,    ROWS, DD, DD);
    gemm_bias_kernel<<<ggrid, 256>>>(key_,  Wk, bk, k,    ROWS, DD, DD);
    gemm_bias_kernel<<<ggrid, 256>>>(value, Wv, bv, v,    ROWS, DD, DD);

    dim3 fgrid(LL / 128, HH, BB);       // (16, 16, 4)
    flash_kernel<<<fgrid, 128>>>(q, k, v, mask, att);

    gemm_bias_kernel<<<ggrid, 256>>>(att, Wo, bo, proj, ROWS, DD, DD);

    ln_kernel<<<ROWS, 256>>>(proj, query, gamma, beta, out);
}

// round 3
// speedup vs baseline: 1.2982x; 1.2982x over previous
#include <cuda_runtime.h>
#include <cuda_bf16.h>
#include <cstdint>
#include <math.h>

#define BB 4
#define LL 2048
#define DD 1024
#define HH 16
#define DHD 64
#define ROWS (BB*LL)   // 8192
#define K2 2048        // split-K: (hi,lo) bf16 pairs interleaved

// ---------------------------------------------------------------------------
// Scratch (__device__ globals: allocation-free rule)
// ---------------------------------------------------------------------------
__device__ float g_q[ROWS*DD];
__device__ float g_k[ROWS*DD];
__device__ float g_v[ROWS*DD];
__device__ float g_att[ROWS*DD];
__device__ float g_proj[ROWS*DD];

__device__ __nv_bfloat16 g_q2[ROWS*K2];
__device__ __nv_bfloat16 g_k2[ROWS*K2];
__device__ __nv_bfloat16 g_v2[ROWS*K2];
__device__ __nv_bfloat16 g_att2[ROWS*K2];
__device__ __nv_bfloat16 g_Wq2[DD*K2];
__device__ __nv_bfloat16 g_Wk2[DD*K2];
__device__ __nv_bfloat16 g_Wv2[DD*K2];
__device__ __nv_bfloat16 g_Wo2[DD*K2];

// ---------------------------------------------------------------------------
__device__ __forceinline__ uint32_t smem_u32(const void* p) {
    uint32_t a;
    asm("{ .reg .u64 t; cvta.to.shared.u64 t, %1; cvt.u32.u64 %0, t; }"
        : "=r"(a) : "l"(p));
    return a;
}

__device__ __forceinline__ void ldm_x4(uint32_t addr, uint32_t* r) {
    asm volatile("ldmatrix.sync.aligned.m8n8.x4.shared.b16 {%0,%1,%2,%3}, [%4];"
        : "=r"(r[0]), "=r"(r[1]), "=r"(r[2]), "=r"(r[3]) : "r"(addr));
}

__device__ __forceinline__ void mma16816(float* c, const uint32_t* a,
                                         uint32_t b0, uint32_t b1) {
    asm volatile(
        "mma.sync.aligned.m16n8k16.row.col.f32.bf16.bf16.f32 "
        "{%0,%1,%2,%3}, {%4,%5,%6,%7}, {%8,%9}, {%0,%1,%2,%3};"
        : "+f"(c[0]), "+f"(c[1]), "+f"(c[2]), "+f"(c[3])
        : "r"(a[0]), "r"(a[1]), "r"(a[2]), "r"(a[3]), "r"(b0), "r"(b1));
}

// ---------------------------------------------------------------------------
// fp32 -> (hi,lo) bf16 split, interleaved along K: out[2k]=hi, out[2k+1]=lo
// ---------------------------------------------------------------------------
__global__ __launch_bounds__(256) void split_kernel(
    const float* __restrict__ in, __nv_bfloat16* __restrict__ out, int n4)
{
    int i = blockIdx.x * blockDim.x + threadIdx.x;
    if (i >= n4) return;
    float4 x = ((const float4*)in)[i];
    union { __nv_bfloat162 h2[4]; uint4 u; } pk;
    {
        __nv_bfloat16 h = __float2bfloat16(x.x);
        pk.h2[0] = __halves2bfloat162(h, __float2bfloat16(x.x - __bfloat162float(h)));
    }
    {
        __nv_bfloat16 h = __float2bfloat16(x.y);
        pk.h2[1] = __halves2bfloat162(h, __float2bfloat16(x.y - __bfloat162float(h)));
    }
    {
        __nv_bfloat16 h = __float2bfloat16(x.z);
        pk.h2[2] = __halves2bfloat162(h, __float2bfloat16(x.z - __bfloat162float(h)));
    }
    {
        __nv_bfloat16 h = __float2bfloat16(x.w);
        pk.h2[3] = __halves2bfloat162(h, __float2bfloat16(x.w - __bfloat162float(h)));
    }
    ((uint4*)out)[i] = pk.u;
}

// ---------------------------------------------------------------------------
// Tensor-core GEMM via mma.sync (bf16 HMMA):
//   C[8192,1024] = A2[8192,K2] @ W2[1024,K2]^T + bias
// 128x128 CTA tile, K-chunk 32, 8 warps (4m x 2n), warp tile 32x64.
// Double-buffered smem (pitch 80B), ldmatrix.x4 fragments, fused bias.
// ---------------------------------------------------------------------------
#define KCH   32
#define NCHNK (K2 / KCH)    // 64
#define PITCH 80            // bytes per smem row (32 bf16 + 16B pad)

__global__ __launch_bounds__(256) void gemm_tc(
    const __nv_bfloat16* __restrict__ A2, const __nv_bfloat16* __restrict__ W2,
    const float* __restrict__ bias, float* __restrict__ C)
{
    __shared__ __align__(16) char smA[2][128 * PITCH];
    __shared__ __align__(16) char smB[2][128 * PITCH];

    const int tid  = threadIdx.x;
    const int lane = tid & 31;
    const int w    = tid >> 5;
    const int wm   = w & 3;      // 0..3  (m groups of 32)
    const int wn   = w >> 2;     // 0..1  (n groups of 64)
    const int m0   = blockIdx.y * 128;
    const int n0   = blockIdx.x * 128;

    // global->smem mapping: thread t handles row r = t/2, 2 x 16B segments
    const int gr    = tid >> 1;
    const int sbase = (tid & 1) * 2;
    const uint4* agp = (const uint4*)(A2 + (size_t)(m0 + gr) * K2);
    const uint4* bgp = (const uint4*)(W2 + (size_t)(n0 + gr) * K2);
    char* stA = smA[0] + gr * PITCH + sbase * 16;
    char* stB = smB[0] + gr * PITCH + sbase * 16;
    const size_t bufStride = 128 * PITCH;

    float acc[2][8][4];
#pragma unroll
    for (int i = 0; i < 2; i++)
#pragma unroll
        for (int j = 0; j < 8; j++)
#pragma unroll
            for (int l = 0; l < 4; l++) acc[i][j][l] = 0.0f;

    // prefetch chunk 0 into buf 0
    {
        uint4 a0 = agp[sbase], a1 = agp[sbase + 1];
        uint4 b0 = bgp[sbase], b1 = bgp[sbase + 1];
        *(uint4*)(stA)      = a0; *(uint4*)(stA + 16) = a1;
        *(uint4*)(stB)      = b0; *(uint4*)(stB + 16) = b1;
    }
    __syncthreads();

    const uint32_t smA0 = smem_u32(smA[0]);
    const uint32_t smB0 = smem_u32(smB[0]);
    // per-thread ldmatrix row addressing: row = (lane&15), byte = (lane>>4)*16
    const uint32_t lrow = (uint32_t)(lane & 15) * PITCH + (uint32_t)(lane >> 4) * 16;

    #pragma unroll 1
    for (int c = 0; c < NCHNK; c++) {
        const int buf = c & 1;

        uint4 pa0, pa1, pb0, pb1;
        if (c + 1 < NCHNK) {
            pa0 = agp[(c + 1) * 4 + sbase];
            pa1 = agp[(c + 1) * 4 + sbase + 1];
            pb0 = bgp[(c + 1) * 4 + sbase];
            pb1 = bgp[(c + 1) * 4 + sbase + 1];
        }

        const uint32_t baseA = smA0 + buf * (uint32_t)bufStride + lrow;
        const uint32_t baseB = smB0 + buf * (uint32_t)bufStride + lrow;

#pragma unroll
        for (int ks = 0; ks < 2; ks++) {
            uint32_t afr[2][4];
#pragma unroll
            for (int mt = 0; mt < 2; mt++)
                ldm_x4(baseA + (wm * 32 + mt * 16) * PITCH + ks * 32, afr[mt]);
#pragma unroll
            for (int ng = 0; ng < 4; ng++) {
                uint32_t bfr[4];
                ldm_x4(baseB + (wn * 64 + ng * 16) * PITCH + ks * 32, bfr);
#pragma unroll
                for (int mt = 0; mt < 2; mt++) {
                    mma16816(acc[mt][ng * 2 + 0], afr[mt], bfr[0], bfr[2]);
                    mma16816(acc[mt][ng * 2 + 1], afr[mt], bfr[1], bfr[3]);
                }
            }
        }

        if (c + 1 < NCHNK) {
            char* dA = stA + ((c + 1) & 1) * bufStride;
            char* dB = stB + ((c + 1) & 1) * bufStride;
            *(uint4*)(dA)      = pa0; *(uint4*)(dA + 16) = pa1;
            *(uint4*)(dB)      = pb0; *(uint4*)(dB + 16) = pb1;
        }
        __syncthreads();
    }

    // epilogue: bias + store
    const int r0 = lane >> 2;
    const int c0 = (lane & 3) * 2;
    const int mrow = m0 + wm * 32;
    const int ncol = n0 + wn * 64;
#pragma unroll
    for (int mt = 0; mt < 2; mt++) {
#pragma unroll
        for (int nt = 0; nt < 8; nt++) {
            int row = mrow + mt * 16 + r0;
            int col = ncol + nt * 8 + c0;
            float2 bb = *(const float2*)(bias + col);
            float2 v0 = { acc[mt][nt][0] + bb.x, acc[mt][nt][1] + bb.y };
            float2 v1 = { acc[mt][nt][2] + bb.x, acc[mt][nt][3] + bb.y };
            *(float2*)(C + (size_t)row * DD + col)       = v0;
            *(float2*)(C + (size_t)(row + 8) * DD + col) = v1;
        }
    }
}

// ---------------------------------------------------------------------------
// Flash attention (unchanged, known-good)
// ---------------------------------------------------------------------------
__global__ __launch_bounds__(128) void flash_kernel(
    const float* __restrict__ Q, const float* __restrict__ Kx,
    const float* __restrict__ V, const int* __restrict__ mask,
    float* __restrict__ O)
{
    const int b  = blockIdx.z;
    const int h  = blockIdx.y;
    const int q0 = blockIdx.x * 128;
    const int tid = threadIdx.x;

    __shared__ float4 Ks[32 * 16];
    __shared__ float4 Vs[32 * 16];
    __shared__ int    Ms[32];

    const int headOff = h * DHD;
    const int rowBase = (b * LL + q0 + tid) * DD + headOff;

    float4 q4[16];
#pragma unroll
    for (int i = 0; i < 16; i++)
        q4[i] = *(const float4*)(Q + rowBase + i * 4);

    float4 acc4[16];
#pragma unroll
    for (int i = 0; i < 16; i++) acc4[i] = make_float4(0.f, 0.f, 0.f, 0.f);

    float m = -1e30f, l = 0.0f;

    for (int k0 = 0; k0 < LL; k0 += 32) {
#pragma unroll
        for (int j = 0; j < 4; j++) {
            int i = tid + 128 * j;
            int r = i >> 4;
            int c = i & 15;
            int g = (b * LL + k0 + r) * DD + headOff + c * 4;
            Ks[r * 16 + c] = *(const float4*)(Kx + g);
            Vs[r * 16 + c] = *(const float4*)(V + g);
        }
        if (tid < 32) Ms[tid] = mask[b * LL + k0 + tid];
        __syncthreads();

        float s[32];
        float tmax = -1e30f;
#pragma unroll
        for (int j = 0; j < 32; j++) {
            float s0 = 0.f, s1 = 0.f, s2 = 0.f, s3 = 0.f;
#pragma unroll
            for (int d = 0; d < 16; d++) {
                float4 kv = Ks[j * 16 + d];
                s0 = fmaf(q4[d].x, kv.x, s0);
                s1 = fmaf(q4[d].y, kv.y, s1);
                s2 = fmaf(q4[d].z, kv.z, s2);
                s3 = fmaf(q4[d].w, kv.w, s3);
            }
            float sv = ((s0 + s1) + (s2 + s3)) * 0.125f;
            sv = (Ms[j] == 0) ? -1e9f : sv;
            s[j] = sv;
            tmax = fmaxf(tmax, sv);
        }

        float mnew  = fmaxf(m, tmax);
        float scale = __expf(m - mnew);
        l *= scale;
#pragma unroll
        for (int i = 0; i < 16; i++) {
            acc4[i].x *= scale; acc4[i].y *= scale;
            acc4[i].z *= scale; acc4[i].w *= scale;
        }

#pragma unroll
        for (int j = 0; j < 32; j++) {
            float p = __expf(s[j] - mnew);
            l += p;
#pragma unroll
            for (int d = 0; d < 16; d++) {
                float4 vv = Vs[j * 16 + d];
                acc4[d].x = fmaf(p, vv.x, acc4[d].x);
                acc4[d].y = fmaf(p, vv.y, acc4[d].y);
                acc4[d].z = fmaf(p, vv.z, acc4[d].z);
                acc4[d].w = fmaf(p, vv.w, acc4[d].w);
            }
        }
        m = mnew;
        __syncthreads();
    }

    float inv = 1.0f / l;
#pragma unroll
    for (int i = 0; i < 16; i++) {
        float4 o;
        o.x = acc4[i].x * inv; o.y = acc4[i].y * inv;
        o.z = acc4[i].z * inv; o.w = acc4[i].w * inv;
        *(float4*)(O + rowBase + i * 4) = o;
    }
}

// ---------------------------------------------------------------------------
// Residual + LayerNorm (unchanged)
// ---------------------------------------------------------------------------
__global__ __launch_bounds__(256) void ln_kernel(
    const float* __restrict__ proj, const float* __restrict__ resid,
    const float* __restrict__ gamma, const float* __restrict__ beta,
    float* __restrict__ out)
{
    const int row = blockIdx.x;
    const int tid = threadIdx.x;

    float4 p = ((const float4*)(proj  + row * DD))[tid];
    float4 r = ((const float4*)(resid + row * DD))[tid];
    float4 x = make_float4(p.x + r.x, p.y + r.y, p.z + r.z, p.w + r.w);

    float s  = x.x + x.y + x.z + x.w;
    float ss = x.x * x.x + x.y * x.y + x.z * x.z + x.w * x.w;

#pragma unroll
    for (int off = 16; off > 0; off >>= 1) {
        s  += __shfl_xor_sync(0xffffffffu, s,  off);
        ss += __shfl_xor_sync(0xffffffffu, ss, off);
    }

    __shared__ float rs[8], rss[8];
    __shared__ float mu_s, rstd_s;
    const int wid  = tid >> 5;
    const int lane = tid & 31;
    if (lane == 0) { rs[wid] = s; rss[wid] = ss; }
    __syncthreads();
    if (tid == 0) {
        float S = 0.f, SS = 0.f;
#pragma unroll
        for (int i = 0; i < 8; i++) { S += rs[i]; SS += rss[i]; }
        float mu  = S * (1.0f / DD);
        float var = SS * (1.0f / DD) - mu * mu;
        mu_s   = mu;
        rstd_s = rsqrtf(var + 1e-5f);
    }
    __syncthreads();

    float mu = mu_s, rstd = rstd_s;
    float4 g  = ((const float4*)gamma)[tid];
    float4 be = ((const float4*)beta)[tid];
    float4 o;
    o.x = (x.x - mu) * rstd * g.x + be.x;
    o.y = (x.y - mu) * rstd * g.y + be.y;
    o.z = (x.z - mu) * rstd * g.z + be.z;
    o.w = (x.w - mu) * rstd * g.w + be.w;
    ((float4*)(out + row * DD))[tid] = o;
}

// ---------------------------------------------------------------------------
extern "C" void kernel_launch(void* const* d_in, const int* in_sizes, int n_in,
                              void* d_out, int out_size)
{
    const float* query = (const float*)d_in[0];
    const float* key_  = (const float*)d_in[1];
    const float* value = (const float*)d_in[2];
    const int*   mask  = (const int*  )d_in[3];
    const float* Wq    = (const float*)d_in[4];
    const float* bq    = (const float*)d_in[5];
    const float* Wk    = (const float*)d_in[6];
    const float* bk    = (const float*)d_in[7];
    const float* Wv    = (const float*)d_in[8];
    const float* bv    = (const float*)d_in[9];
    const float* Wo    = (const float*)d_in[10];
    const float* bo    = (const float*)d_in[11];
    const float* gamma = (const float*)d_in[12];
    const float* beta  = (const float*)d_in[13];
    float* out = (float*)d_out;

    float *q, *k, *v, *att, *proj;
    cudaGetSymbolAddress((void**)&q,    g_q);
    cudaGetSymbolAddress((void**)&k,    g_k);
    cudaGetSymbolAddress((void**)&v,    g_v);
    cudaGetSymbolAddress((void**)&att,  g_att);
    cudaGetSymbolAddress((void**)&proj, g_proj);

    __nv_bfloat16 *q2, *k2, *v2, *att2, *Wq2, *Wk2, *Wv2, *Wo2;
    cudaGetSymbolAddress((void**)&q2,   g_q2);
    cudaGetSymbolAddress((void**)&k2,   g_k2);
    cudaGetSymbolAddress((void**)&v2,   g_v2);
    cudaGetSymbolAddress((void**)&att2, g_att2);
    cudaGetSymbolAddress((void**)&Wq2,  g_Wq2);
    cudaGetSymbolAddress((void**)&Wk2,  g_Wk2);
    cudaGetSymbolAddress((void**)&Wv2,  g_Wv2);
    cudaGetSymbolAddress((void**)&Wo2,  g_Wo2);

    const int nInp4 = ROWS * DD / 4;
    const int nW4   = DD * DD / 4;
    split_kernel<<<(nInp4 + 255) / 256, 256>>>(query, q2, nInp4);
    split_kernel<<<(nInp4 + 255) / 256, 256>>>(key_,  k2, nInp4);
    split_kernel<<<(nInp4 + 255) / 256, 256>>>(value, v2, nInp4);
    split_kernel<<<(nW4   + 255) / 256, 256>>>(Wq, Wq2, nW4);
    split_kernel<<<(nW4   + 255) / 256, 256>>>(Wk, Wk2, nW4);
    split_kernel<<<(nW4   + 255) / 256, 256>>>(Wv, Wv2, nW4);
    split_kernel<<<(nW4   + 255) / 256, 256>>>(Wo, Wo2, nW4);

    dim3 ggrid(DD / 128, ROWS / 128);   // (8, 64)
    gemm_tc<<<ggrid, 256>>>(q2, Wq2, bq, q);
    gemm_tc<<<ggrid, 256>>>(k2, Wk2, bk, k);
    gemm_tc<<<ggrid, 256>>>(v2, Wv2, bv, v);

    dim3 fgrid(LL / 128, HH, BB);       // (16, 16, 4)
    flash_kernel<<<fgrid, 128>>>(q, k, v, mask, att);

    split_kernel<<<(nInp4 + 255) / 256, 256>>>(att, att2, nInp4);
    gemm_tc<<<ggrid, 256>>>(att2, Wo2, bo, proj);

    ln_kernel<<<ROWS, 256>>>(proj, query, gamma, beta, out);
}

// round 6
// speedup vs baseline: 3.9536x; 3.0455x over previous
#include <cuda_runtime.h>
#include <cuda_bf16.h>
#include <cstdint>
#include <math.h>

#define BB 4
#define LL 2048
#define DD 1024
#define HH 16
#define DHD 64
#define ROWS (BB*LL)   // 8192
#define K2 2048        // split-K: (hi,lo) bf16 pairs interleaved

// ---------------------------------------------------------------------------
// Scratch (__device__ globals: allocation-free rule)
// ---------------------------------------------------------------------------
__device__ float g_proj[ROWS*DD];

__device__ __nv_bfloat16 g_q2[ROWS*K2];      // split inputs for projections
__device__ __nv_bfloat16 g_k2[ROWS*K2];
__device__ __nv_bfloat16 g_v2[ROWS*K2];
__device__ __nv_bfloat16 g_att2[ROWS*K2];    // flash output, (hi,lo) split
__device__ __nv_bfloat16 g_Wq2[DD*K2];
__device__ __nv_bfloat16 g_Wk2[DD*K2];
__device__ __nv_bfloat16 g_Wv2[DD*K2];
__device__ __nv_bfloat16 g_Wo2[DD*K2];

__device__ __nv_bfloat16 g_qbf[BB*HH*LL*DHD];  // [b,h,l,64] bf16
__device__ __nv_bfloat16 g_kbf[BB*HH*LL*DHD];  // [b,h,l,64] bf16
__device__ __nv_bfloat16 g_vt [BB*HH*DHD*LL];  // [b,h,64,L] bf16 (transposed)

// ---------------------------------------------------------------------------
__device__ __forceinline__ uint32_t smem_u32(const void* p) {
    uint32_t a;
    asm("{ .reg .u64 t; cvta.to.shared.u64 t, %1; cvt.u32.u64 %0, t; }"
        : "=r"(a) : "l"(p));
    return a;
}

__device__ __forceinline__ void ldm_x4(uint32_t addr, uint32_t* r) {
    asm volatile("ldmatrix.sync.aligned.m8n8.x4.shared.b16 {%0,%1,%2,%3}, [%4];"
        : "=r"(r[0]), "=r"(r[1]), "=r"(r[2]), "=r"(r[3]) : "r"(addr));
}

__device__ __forceinline__ void mma16816(float* c, const uint32_t* a,
                                         uint32_t b0, uint32_t b1) {
    asm volatile(
        "mma.sync.aligned.m16n8k16.row.col.f32.bf16.bf16.f32 "
        "{%0,%1,%2,%3}, {%4,%5,%6,%7}, {%8,%9}, {%0,%1,%2,%3};"
        : "+f"(c[0]), "+f"(c[1]), "+f"(c[2]), "+f"(c[3])
        : "r"(a[0]), "r"(a[1]), "r"(a[2]), "r"(a[3]), "r"(b0), "r"(b1));
}

__device__ __forceinline__ uint32_t pack_bf162(float lo, float hi) {
    __nv_bfloat162 t = __floats2bfloat162_rn(lo, hi); // .x = lo (low address)
    return *(uint32_t*)&t;
}

// ---------------------------------------------------------------------------
// fp32 -> (hi,lo) bf16 split, interleaved along K
// ---------------------------------------------------------------------------
__global__ __launch_bounds__(256) void split_kernel(
    const float* __restrict__ in, __nv_bfloat16* __restrict__ out, int n4)
{
    int i = blockIdx.x * blockDim.x + threadIdx.x;
    if (i >= n4) return;
    float4 x = ((const float4*)in)[i];
    union { __nv_bfloat162 h2[4]; uint4 u; } pk;
    {
        __nv_bfloat16 h = __float2bfloat16(x.x);
        pk.h2[0] = __halves2bfloat162(h, __float2bfloat16(x.x - __bfloat162float(h)));
    }
    {
        __nv_bfloat16 h = __float2bfloat16(x.y);
        pk.h2[1] = __halves2bfloat162(h, __float2bfloat16(x.y - __bfloat162float(h)));
    }
    {
        __nv_bfloat16 h = __float2bfloat16(x.z);
        pk.h2[2] = __halves2bfloat162(h, __float2bfloat16(x.z - __bfloat162float(h)));
    }
    {
        __nv_bfloat16 h = __float2bfloat16(x.w);
        pk.h2[3] = __halves2bfloat162(h, __float2bfloat16(x.w - __bfloat162float(h)));
    }
    ((uint4*)out)[i] = pk.u;
}

// ---------------------------------------------------------------------------
// Tensor-core GEMM: C = A2[8192,K2] @ W2[1024,K2]^T + bias, templated epilogue
// MODE 0: fp32 out [8192,1024]
// MODE 1: bf16 out [b,h,l,64]
// MODE 2: bf16 out transposed [b,h,64,L] (V)
// ---------------------------------------------------------------------------
#define KCH   32
#define NCHNK (K2 / KCH)    // 64
#define PITCH 80            // bytes per smem row (32 bf16 + 16B pad)
#define BUFSZ (128*PITCH)   // 10240

template<int MODE>
__global__ __launch_bounds__(256) void gemm_tc(
    const __nv_bfloat16* __restrict__ A2, const __nv_bfloat16* __restrict__ W2,
    const float* __restrict__ bias, void* __restrict__ outp)
{
    __shared__ __align__(16) char smem_all[4*BUFSZ];   // A0 A1 B0 B1 / stage

    const int tid  = threadIdx.x;
    const int lane = tid & 31;
    const int w    = tid >> 5;
    const int wm   = w & 3;
    const int wn   = w >> 2;
    const int m0   = blockIdx.y * 128;
    const int n0   = blockIdx.x * 128;

    const int gr    = tid >> 1;
    const int sbase = (tid & 1) * 2;
    const uint4* agp = (const uint4*)(A2 + (size_t)(m0 + gr) * K2);
    const uint4* bgp = (const uint4*)(W2 + (size_t)(n0 + gr) * K2);
    char* stA = smem_all + gr * PITCH + sbase * 16;
    char* stB = smem_all + 2 * BUFSZ + gr * PITCH + sbase * 16;

    float acc[2][8][4];
#pragma unroll
    for (int i = 0; i < 2; i++)
#pragma unroll
        for (int j = 0; j < 8; j++)
#pragma unroll
            for (int l = 0; l < 4; l++) acc[i][j][l] = 0.0f;

    {
        uint4 a0 = agp[sbase], a1 = agp[sbase + 1];
        uint4 b0 = bgp[sbase], b1 = bgp[sbase + 1];
        *(uint4*)(stA)      = a0; *(uint4*)(stA + 16) = a1;
        *(uint4*)(stB)      = b0; *(uint4*)(stB + 16) = b1;
    }
    __syncthreads();

    const uint32_t smBase = smem_u32(smem_all);
    const uint32_t lrow = (uint32_t)(lane & 15) * PITCH + (uint32_t)(lane >> 4) * 16;

    #pragma unroll 1
    for (int c = 0; c < NCHNK; c++) {
        const int buf = c & 1;

        uint4 pa0, pa1, pb0, pb1;
        if (c + 1 < NCHNK) {
            pa0 = agp[(c + 1) * 4 + sbase];
            pa1 = agp[(c + 1) * 4 + sbase + 1];
            pb0 = bgp[(c + 1) * 4 + sbase];
            pb1 = bgp[(c + 1) * 4 + sbase + 1];
        }

        const uint32_t baseA = smBase + buf * BUFSZ + lrow;
        const uint32_t baseB = smBase + 2 * BUFSZ + buf * BUFSZ + lrow;

#pragma unroll
        for (int ks = 0; ks < 2; ks++) {
            uint32_t afr[2][4];
#pragma unroll
            for (int mt = 0; mt < 2; mt++)
                ldm_x4(baseA + (wm * 32 + mt * 16) * PITCH + ks * 32, afr[mt]);
#pragma unroll
            for (int ng = 0; ng < 4; ng++) {
                uint32_t bfr[4];
                ldm_x4(baseB + (wn * 64 + ng * 16) * PITCH + ks * 32, bfr);
#pragma unroll
                for (int mt = 0; mt < 2; mt++) {
                    mma16816(acc[mt][ng * 2 + 0], afr[mt], bfr[0], bfr[2]);
                    mma16816(acc[mt][ng * 2 + 1], afr[mt], bfr[1], bfr[3]);
                }
            }
        }

        if (c + 1 < NCHNK) {
            char* dA = stA + ((c + 1) & 1) * BUFSZ;
            char* dB = stB + ((c + 1) & 1) * BUFSZ;
            *(uint4*)(dA)      = pa0; *(uint4*)(dA + 16) = pa1;
            *(uint4*)(dB)      = pb0; *(uint4*)(dB + 16) = pb1;
        }
        __syncthreads();
    }

    const int r0 = lane >> 2;
    const int c0 = (lane & 3) * 2;

    if (MODE == 0) {
        float* C = (float*)outp;
#pragma unroll
        for (int mt = 0; mt < 2; mt++) {
#pragma unroll
            for (int nt = 0; nt < 8; nt++) {
                int row = m0 + wm * 32 + mt * 16 + r0;
                int col = n0 + wn * 64 + nt * 8 + c0;
                float2 bb = *(const float2*)(bias + col);
                float2 v0 = { acc[mt][nt][0] + bb.x, acc[mt][nt][1] + bb.y };
                float2 v1 = { acc[mt][nt][2] + bb.x, acc[mt][nt][3] + bb.y };
                *(float2*)(C + (size_t)row * DD + col)       = v0;
                *(float2*)(C + (size_t)(row + 8) * DD + col) = v1;
            }
        }
    } else if (MODE == 1) {
        __nv_bfloat162* C = (__nv_bfloat162*)outp;
#pragma unroll
        for (int mt = 0; mt < 2; mt++) {
#pragma unroll
            for (int nt = 0; nt < 8; nt++) {
                int row = m0 + wm * 32 + mt * 16 + r0;
                int col = n0 + wn * 64 + nt * 8 + c0;
                float2 bb = *(const float2*)(bias + col);
                int bI = row >> 11, lI = row & (LL - 1);
                int hI = col >> 6,  dI = col & 63;
                size_t off = ((((size_t)bI * HH + hI) * LL + lI) * 64 + dI) >> 1;
                C[off] = __floats2bfloat162_rn(
                    acc[mt][nt][0] + bb.x, acc[mt][nt][1] + bb.y);
                C[off + 256] = __floats2bfloat162_rn(          // row+8: +8*64/2
                    acc[mt][nt][2] + bb.x, acc[mt][nt][3] + bb.y);
            }
        }
    } else {
        // MODE 2: transpose via smem stage: stage[col][row], pitch 136 bf16
        __nv_bfloat16* stage = (__nv_bfloat16*)smem_all;
#pragma unroll
        for (int mt = 0; mt < 2; mt++) {
#pragma unroll
            for (int nt = 0; nt < 8; nt++) {
                int rl = wm * 32 + mt * 16 + r0;
                int cl = wn * 64 + nt * 8 + c0;
                float2 bb = *(const float2*)(bias + n0 + cl);
                stage[cl       * 136 + rl]     = __float2bfloat16(acc[mt][nt][0] + bb.x);
                stage[(cl + 1) * 136 + rl]     = __float2bfloat16(acc[mt][nt][1] + bb.y);
                stage[cl       * 136 + rl + 8] = __float2bfloat16(acc[mt][nt][2] + bb.x);
                stage[(cl + 1) * 136 + rl + 8] = __float2bfloat16(acc[mt][nt][3] + bb.y);
            }
        }
        __syncthreads();
        __nv_bfloat16* VT = (__nv_bfloat16*)outp;
        const int bI = m0 >> 11, lI = m0 & (LL - 1);
        const int drow = tid >> 1, seg = tid & 1;
        const int hI = (n0 + drow) >> 6, dI = (n0 + drow) & 63;
        const uint4* src = (const uint4*)(stage + drow * 136 + seg * 64);
        uint4* dst = (uint4*)(VT + (((size_t)bI * HH + hI) * DHD + dI) * LL
                              + lI + seg * 64);
#pragma unroll
        for (int i = 0; i < 8; i++) dst[i] = src[i];
    }
}

// ---------------------------------------------------------------------------
// Tensor-core flash attention.
// Qb/Kb: [b,h,l,64] bf16.  Vt: [b,h,64,L] bf16.  Out: att2 (hi,lo) split.
// CTA: 128 thr (4 warps), 64 q-rows (16/warp), key tile 128.
// ---------------------------------------------------------------------------
#define QP 144   // smem pitch bytes for 64-bf16 rows
#define VP 272   // smem pitch bytes for 128-bf16 rows

__global__ __launch_bounds__(128) void flash_tc(
    const __nv_bfloat16* __restrict__ Qb, const __nv_bfloat16* __restrict__ Kb,
    const __nv_bfloat16* __restrict__ Vt, const int* __restrict__ mask,
    __nv_bfloat16* __restrict__ att2)
{
    __shared__ __align__(16) char sQ[64 * QP];
    __shared__ __align__(16) char sK[128 * QP];
    __shared__ __align__(16) char sV[64 * VP];
    __shared__ int Ms[128];

    const int b = blockIdx.z, h = blockIdx.y;
    const int q0 = blockIdx.x * 64;
    const int tid = threadIdx.x, lane = tid & 31, w = tid >> 5;
    const size_t bh = (size_t)b * HH + h;

    // Q tile [64][64]
    {
        const char* qsrc = (const char*)(Qb + (bh * LL + q0) * 64);
        for (int i = tid; i < 512; i += 128) {
            int r = i >> 3, s = i & 7;
            *(uint4*)(sQ + r * QP + s * 16) = *(const uint4*)(qsrc + r * 128 + s * 16);
        }
    }
    __syncthreads();

    uint32_t qf[4][4];
    {
        uint32_t base = smem_u32(sQ) + (w * 16 + (lane & 15)) * QP + (lane >> 4) * 16;
#pragma unroll
        for (int ks = 0; ks < 4; ks++) ldm_x4(base + ks * 32, qf[ks]);
    }

    float O[8][4];
#pragma unroll
    for (int g = 0; g < 8; g++)
#pragma unroll
        for (int l = 0; l < 4; l++) O[g][l] = 0.0f;
    float m0r = -1e30f, m1r = -1e30f, l0 = 0.0f, l1 = 0.0f;

    const char* ksrc0 = (const char*)(Kb + bh * LL * 64);
    const char* vsrc0 = (const char*)(Vt + bh * DHD * LL);
    const int c0 = (lane & 3) * 2;

    #pragma unroll 1
    for (int kt = 0; kt < LL; kt += 128) {
        __syncthreads();
        const char* ksrc = ksrc0 + (size_t)kt * 128;
        for (int i = tid; i < 1024; i += 128) {
            int r = i >> 3, s = i & 7;
            *(uint4*)(sK + r * QP + s * 16) = *(const uint4*)(ksrc + r * 128 + s * 16);
        }
        for (int i = tid; i < 1024; i += 128) {
            int r = i >> 4, s = i & 15;
            *(uint4*)(sV + r * VP + s * 16) =
                *(const uint4*)(vsrc0 + ((size_t)r * LL + kt) * 2 + s * 16);
        }
        Ms[tid] = mask[b * LL + kt + tid];
        __syncthreads();

        // scores S[16 nfrags][4]
        float s[16][4];
        {
            uint32_t kbase = smem_u32(sK) + (lane & 15) * QP + (lane >> 4) * 16;
#pragma unroll
            for (int j = 0; j < 8; j++) {
                float a0[4] = {0, 0, 0, 0}, a1[4] = {0, 0, 0, 0};
#pragma unroll
                for (int ks = 0; ks < 4; ks++) {
                    uint32_t bf[4];
                    ldm_x4(kbase + j * 16 * QP + ks * 32, bf);
                    mma16816(a0, qf[ks], bf[0], bf[2]);
                    mma16816(a1, qf[ks], bf[1], bf[3]);
                }
#pragma unroll
                for (int l = 0; l < 4; l++) { s[2*j][l] = a0[l]; s[2*j+1][l] = a1[l]; }
            }
        }

        // scale + mask
#pragma unroll
        for (int j = 0; j < 16; j++) {
            int key = j * 8 + c0;
            bool u0 = Ms[key] != 0, u1 = Ms[key + 1] != 0;
            s[j][0] = u0 ? s[j][0] * 0.125f : -1e9f;
            s[j][1] = u1 ? s[j][1] * 0.125f : -1e9f;
            s[j][2] = u0 ? s[j][2] * 0.125f : -1e9f;
            s[j][3] = u1 ? s[j][3] * 0.125f : -1e9f;
        }

        // row maxes (rows r and r+8), reduce over quad lanes
        float t0 = -1e30f, t1 = -1e30f;
#pragma unroll
        for (int j = 0; j < 16; j++) {
            t0 = fmaxf(t0, fmaxf(s[j][0], s[j][1]));
            t1 = fmaxf(t1, fmaxf(s[j][2], s[j][3]));
        }
        t0 = fmaxf(t0, __shfl_xor_sync(0xffffffffu, t0, 1));
        t0 = fmaxf(t0, __shfl_xor_sync(0xffffffffu, t0, 2));
        t1 = fmaxf(t1, __shfl_xor_sync(0xffffffffu, t1, 1));
        t1 = fmaxf(t1, __shfl_xor_sync(0xffffffffu, t1, 2));

        float mn0 = fmaxf(m0r, t0), mn1 = fmaxf(m1r, t1);
        float sc0 = __expf(m0r - mn0), sc1 = __expf(m1r - mn1);
        m0r = mn0; m1r = mn1;
        l0 *= sc0; l1 *= sc1;
#pragma unroll
        for (int g = 0; g < 8; g++) {
            O[g][0] *= sc0; O[g][1] *= sc0; O[g][2] *= sc1; O[g][3] *= sc1;
        }

        float rs0 = 0.0f, rs1 = 0.0f;
#pragma unroll
        for (int j = 0; j < 16; j++) {
            s[j][0] = __expf(s[j][0] - mn0);
            s[j][1] = __expf(s[j][1] - mn0);
            s[j][2] = __expf(s[j][2] - mn1);
            s[j][3] = __expf(s[j][3] - mn1);
            rs0 += s[j][0] + s[j][1];
            rs1 += s[j][2] + s[j][3];
        }
        rs0 += __shfl_xor_sync(0xffffffffu, rs0, 1);
        rs0 += __shfl_xor_sync(0xffffffffu, rs0, 2);
        rs1 += __shfl_xor_sync(0xffffffffu, rs1, 1);
        rs1 += __shfl_xor_sync(0xffffffffu, rs1, 2);
        l0 += rs0; l1 += rs1;

        // PV: O += P @ V  (A from S frags, B from sV)
        {
            uint32_t vbase = smem_u32(sV) + (lane & 15) * VP + (lane >> 4) * 16;
#pragma unroll
            for (int t = 0; t < 8; t++) {
                uint32_t a[4];
                a[0] = pack_bf162(s[2*t][0],   s[2*t][1]);
                a[1] = pack_bf162(s[2*t][2],   s[2*t][3]);
                a[2] = pack_bf162(s[2*t+1][0], s[2*t+1][1]);
                a[3] = pack_bf162(s[2*t+1][2], s[2*t+1][3]);
#pragma unroll
                for (int g = 0; g < 4; g++) {
                    uint32_t bf[4];
                    ldm_x4(vbase + g * 16 * VP + t * 32, bf);
                    mma16816(O[2*g],     a, bf[0], bf[2]);
                    mma16816(O[2*g + 1], a, bf[1], bf[3]);
                }
            }
        }
    }

    // normalize + write att2 as (hi,lo) split pairs
    float inv0 = 1.0f / l0, inv1 = 1.0f / l1;
    const int r0 = lane >> 2;
    const size_t row0 = (size_t)b * LL + q0 + w * 16 + r0;
#pragma unroll
    for (int g = 0; g < 8; g++) {
        int d = 8 * g + c0;
        int cb = 2 * (h * DHD + d);
        float v0 = O[g][0] * inv0, v1 = O[g][1] * inv0;
        float v2 = O[g][2] * inv1, v3 = O[g][3] * inv1;
        union { __nv_bfloat162 h2[2]; uint2 u; } p0, p1;
        {
            __nv_bfloat16 hh = __float2bfloat16(v0);
            p0.h2[0] = __halves2bfloat162(hh, __float2bfloat16(v0 - __bfloat162float(hh)));
            hh = __float2bfloat16(v1);
            p0.h2[1] = __halves2bfloat162(hh, __float2bfloat16(v1 - __bfloat162float(hh)));
            hh = __float2bfloat16(v2);
            p1.h2[0] = __halves2bfloat162(hh, __float2bfloat16(v2 - __bfloat162float(hh)));
            hh = __float2bfloat16(v3);
            p1.h2[1] = __halves2bfloat162(hh, __float2bfloat16(v3 - __bfloat162float(hh)));
        }
        *(uint2*)(att2 + row0 * K2 + cb)       = p0.u;
        *(uint2*)(att2 + (row0 + 8) * K2 + cb) = p1.u;
    }
}

// ---------------------------------------------------------------------------
// Residual + LayerNorm
// ---------------------------------------------------------------------------
__global__ __launch_bounds__(256) void ln_kernel(
    const float* __restrict__ proj, const float* __restrict__ resid,
    const float* __restrict__ gamma, const float* __restrict__ beta,
    float* __restrict__ out)
{
    const int row = blockIdx.x;
    const int tid = threadIdx.x;

    float4 p = ((const float4*)(proj  + row * DD))[tid];
    float4 r = ((const float4*)(resid + row * DD))[tid];
    float4 x = make_float4(p.x + r.x, p.y + r.y, p.z + r.z, p.w + r.w);

    float s  = x.x + x.y + x.z + x.w;
    float ss = x.x * x.x + x.y * x.y + x.z * x.z + x.w * x.w;

#pragma unroll
    for (int off = 16; off > 0; off >>= 1) {
        s  += __shfl_xor_sync(0xffffffffu, s,  off);
        ss += __shfl_xor_sync(0xffffffffu, ss, off);
    }

    __shared__ float rs[8], rss[8];
    __shared__ float mu_s, rstd_s;
    const int wid  = tid >> 5;
    const int lane = tid & 31;
    if (lane == 0) { rs[wid] = s; rss[wid] = ss; }
    __syncthreads();
    if (tid == 0) {
        float S = 0.f, SS = 0.f;
#pragma unroll
        for (int i = 0; i < 8; i++) { S += rs[i]; SS += rss[i]; }
        float mu  = S * (1.0f / DD);
        float var = SS * (1.0f / DD) - mu * mu;
        mu_s   = mu;
        rstd_s = rsqrtf(var + 1e-5f);
    }
    __syncthreads();

    float mu = mu_s, rstd = rstd_s;
    float4 g  = ((const float4*)gamma)[tid];
    float4 be = ((const float4*)beta)[tid];
    float4 o;
    o.x = (x.x - mu) * rstd * g.x + be.x;
    o.y = (x.y - mu) * rstd * g.y + be.y;
    o.z = (x.z - mu) * rstd * g.z + be.z;
    o.w = (x.w - mu) * rstd * g.w + be.w;
    ((float4*)(out + row * DD))[tid] = o;
}

// ---------------------------------------------------------------------------
extern "C" void kernel_launch(void* const* d_in, const int* in_sizes, int n_in,
                              void* d_out, int out_size)
{
    const float* query = (const float*)d_in[0];
    const float* key_  = (const float*)d_in[1];
    const float* value = (const float*)d_in[2];
    const int*   mask  = (const int*  )d_in[3];
    const float* Wq    = (const float*)d_in[4];
    const float* bq    = (const float*)d_in[5];
    const float* Wk    = (const float*)d_in[6];
    const float* bk    = (const float*)d_in[7];
    const float* Wv    = (const float*)d_in[8];
    const float* bv    = (const float*)d_in[9];
    const float* Wo    = (const float*)d_in[10];
    const float* bo    = (const float*)d_in[11];
    const float* gamma = (const float*)d_in[12];
    const float* beta  = (const float*)d_in[13];
    float* out = (float*)d_out;

    float* proj;
    cudaGetSymbolAddress((void**)&proj, g_proj);
    __nv_bfloat16 *q2, *k2, *v2, *att2, *Wq2, *Wk2, *Wv2, *Wo2, *qbf, *kbf, *vt;
    cudaGetSymbolAddress((void**)&q2,   g_q2);
    cudaGetSymbolAddress((void**)&k2,   g_k2);
    cudaGetSymbolAddress((void**)&v2,   g_v2);
    cudaGetSymbolAddress((void**)&att2, g_att2);
    cudaGetSymbolAddress((void**)&Wq2,  g_Wq2);
    cudaGetSymbolAddress((void**)&Wk2,  g_Wk2);
    cudaGetSymbolAddress((void**)&Wv2,  g_Wv2);
    cudaGetSymbolAddress((void**)&Wo2,  g_Wo2);
    cudaGetSymbolAddress((void**)&qbf,  g_qbf);
    cudaGetSymbolAddress((void**)&kbf,  g_kbf);
    cudaGetSymbolAddress((void**)&vt,   g_vt);

    const int nInp4 = ROWS * DD / 4;
    const int nW4   = DD * DD / 4;
    split_kernel<<<(nInp4 + 255) / 256, 256>>>(query, q2, nInp4);
    split_kernel<<<(nInp4 + 255) / 256, 256>>>(key_,  k2, nInp4);
    split_kernel<<<(nInp4 + 255) / 256, 256>>>(value, v2, nInp4);
    split_kernel<<<(nW4   + 255) / 256, 256>>>(Wq, Wq2, nW4);
    split_kernel<<<(nW4   + 255) / 256, 256>>>(Wk, Wk2, nW4);
    split_kernel<<<(nW4   + 255) / 256, 256>>>(Wv, Wv2, nW4);
    split_kernel<<<(nW4   + 255) / 256, 256>>>(Wo, Wo2, nW4);

    dim3 ggrid(DD / 128, ROWS / 128);   // (8, 64)
    gemm_tc<1><<<ggrid, 256>>>(q2, Wq2, bq, qbf);
    gemm_tc<1><<<ggrid, 256>>>(k2, Wk2, bk, kbf);
    gemm_tc<2><<<ggrid, 256>>>(v2, Wv2, bv, vt);

    dim3 fgrid(LL / 64, HH, BB);        // (32, 16, 4)
    flash_tc<<<fgrid, 128>>>(qbf, kbf, vt, mask, att2);

    gemm_tc<0><<<ggrid, 256>>>(att2, Wo2, bo, proj);

    ln_kernel<<<ROWS, 256>>>(proj, query, gamma, beta, out);
}